// round 1
// baseline (speedup 1.0000x reference)
#include <cuda_runtime.h>

#define H   128
#define H2  256
#define NMX 40000

// Static scratch (allocations are forbidden).
__device__ __align__(16) float g_accL[(size_t)NMX * H];
__device__ __align__(16) float g_accR[(size_t)NMX * H];
__device__ float g_cnt[NMX];

// ---------------------------------------------------------------------------
// K0: zero accumulators + counts
// ---------------------------------------------------------------------------
__global__ void k_zero() {
    int i = blockIdx.x * blockDim.x + threadIdx.x;
    int total = NMX * H;
    for (int p = i; p < total; p += gridDim.x * blockDim.x) {
        g_accL[p] = 0.f;
        g_accR[p] = 0.f;
    }
    if (i < NMX) g_cnt[i] = 0.f;
}

// ---------------------------------------------------------------------------
// K1: per-edge LayerNorm -> 2x GEMV (as tiled GEMM) -> sigmoid -> atomic scatter
// Tile: 64 edges x 128 cols, 256 threads (8 warps).
//   warp = edge-group of 8 edges, lane = col-group of 4 cols.
// ---------------------------------------------------------------------------
__global__ void __launch_bounds__(256) k_gates(
    const float* __restrict__ y,
    const int*   __restrict__ dst,
    const float* __restrict__ ln_g, const float* __restrict__ ln_b,
    const float* __restrict__ Wl,   const float* __restrict__ bl,
    const float* __restrict__ Wr,   const float* __restrict__ br,
    int E)
{
    __shared__ float yn_s[64][H];   // 32 KB
    __shared__ int   dst_s[64];

    const int t    = threadIdx.x;
    const int warp = t >> 5;
    const int lane = t & 31;
    const long long base = (long long)blockIdx.x * 64;

    if (t < 64) {
        long long e = base + t;
        int d = (e < E) ? dst[e] : -1;
        dst_s[t] = d;
        if (d >= 0) atomicAdd(&g_cnt[d], 1.0f);
    }

    // LayerNorm: each warp handles 8 edges
    #pragma unroll
    for (int i = 0; i < 8; i++) {
        int el = warp * 8 + i;
        long long e = base + el;
        float4 v = make_float4(0.f, 0.f, 0.f, 0.f);
        if (e < E) v = *(const float4*)&y[e * H + lane * 4];
        float s  = v.x + v.y + v.z + v.w;
        float ss = v.x * v.x + v.y * v.y + v.z * v.z + v.w * v.w;
        #pragma unroll
        for (int o = 16; o; o >>= 1) {
            s  += __shfl_xor_sync(0xffffffffu, s,  o);
            ss += __shfl_xor_sync(0xffffffffu, ss, o);
        }
        float mu  = s * (1.f / H);
        float var = ss * (1.f / H) - mu * mu;
        float rs  = rsqrtf(var + 1e-5f);
        int p = lane * 4;
        float4 g = *(const float4*)&ln_g[p];
        float4 b = *(const float4*)&ln_b[p];
        float4 o4;
        o4.x = (v.x - mu) * rs * g.x + b.x;
        o4.y = (v.y - mu) * rs * g.y + b.y;
        o4.z = (v.z - mu) * rs * g.z + b.z;
        o4.w = (v.w - mu) * rs * g.w + b.w;
        *(float4*)&yn_s[el][p] = o4;
    }
    __syncthreads();

    // Register-tiled GEMM: each thread -> 8 edges x 4 cols, both matrices
    float accL[8][4], accR[8][4];
    #pragma unroll
    for (int i = 0; i < 8; i++)
        #pragma unroll
        for (int c = 0; c < 4; c++) { accL[i][c] = 0.f; accR[i][c] = 0.f; }

    const int j0 = lane * 4;
    const int e0 = warp * 8;

    #pragma unroll 4
    for (int k = 0; k < H; k++) {
        float4 wl = *(const float4*)&Wl[k * H + j0];
        float4 wr = *(const float4*)&Wr[k * H + j0];
        #pragma unroll
        for (int i = 0; i < 8; i++) {
            float a = yn_s[e0 + i][k];
            accL[i][0] += a * wl.x; accL[i][1] += a * wl.y;
            accL[i][2] += a * wl.z; accL[i][3] += a * wl.w;
            accR[i][0] += a * wr.x; accR[i][1] += a * wr.y;
            accR[i][2] += a * wr.z; accR[i][3] += a * wr.w;
        }
    }

    float4 blv = *(const float4*)&bl[j0];
    float4 brv = *(const float4*)&br[j0];

    #pragma unroll
    for (int i = 0; i < 8; i++) {
        int d = dst_s[e0 + i];
        if (d < 0) continue;
        float* pl = &g_accL[(long long)d * H + j0];
        float* pr = &g_accR[(long long)d * H + j0];
        float sl0 = 1.f / (1.f + __expf(-(accL[i][0] + blv.x)));
        float sl1 = 1.f / (1.f + __expf(-(accL[i][1] + blv.y)));
        float sl2 = 1.f / (1.f + __expf(-(accL[i][2] + blv.z)));
        float sl3 = 1.f / (1.f + __expf(-(accL[i][3] + blv.w)));
        float sr0 = 1.f / (1.f + __expf(-(accR[i][0] + brv.x)));
        float sr1 = 1.f / (1.f + __expf(-(accR[i][1] + brv.y)));
        float sr2 = 1.f / (1.f + __expf(-(accR[i][2] + brv.z)));
        float sr3 = 1.f / (1.f + __expf(-(accR[i][3] + brv.w)));
        atomicAdd(pl + 0, sl0); atomicAdd(pl + 1, sl1);
        atomicAdd(pl + 2, sl2); atomicAdd(pl + 3, sl3);
        atomicAdd(pr + 0, sr0); atomicAdd(pr + 1, sr1);
        atomicAdd(pr + 2, sr2); atomicAdd(pr + 3, sr3);
    }
}

// ---------------------------------------------------------------------------
// K2: mean = sum / max(cnt, 1)
// ---------------------------------------------------------------------------
__global__ void k_norm() {
    int i = blockIdx.x * blockDim.x + threadIdx.x;
    if (i >= NMX * H) return;
    float c = g_cnt[i >> 7];
    float inv = 1.f / fmaxf(c, 1.f);
    g_accL[i] *= inv;
    g_accR[i] *= inv;
}

// ---------------------------------------------------------------------------
// K3: gather concat -> LN(256) -> GEMM (32e x 128c x K256) -> ELU -> dot W2
// 256 threads: warp = 4 edges, lane = col-group of 4.
// ---------------------------------------------------------------------------
__global__ void __launch_bounds__(256) k_mlp(
    const int*   __restrict__ src,
    const int*   __restrict__ dst,
    const float* __restrict__ g2, const float* __restrict__ b2ln,
    const float* __restrict__ W1, const float* __restrict__ b1,
    const float* __restrict__ W2, const float* __restrict__ b2,
    float* __restrict__ out, int E)
{
    __shared__ float hn_s[32][H2];   // 32 KB

    const int t    = threadIdx.x;
    const int warp = t >> 5;
    const int lane = t & 31;
    const long long base = (long long)blockIdx.x * 32;
    const int p = lane * 4;

    // Gather + LayerNorm over 256
    #pragma unroll
    for (int i = 0; i < 4; i++) {
        int el = warp * 4 + i;
        long long e = base + el;
        float4 a = make_float4(0.f, 0.f, 0.f, 0.f);
        float4 r = make_float4(0.f, 0.f, 0.f, 0.f);
        if (e < E) {
            int sn = src[e], dn = dst[e];
            a = *(const float4*)&g_accL[(long long)sn * H + p];
            r = *(const float4*)&g_accR[(long long)dn * H + p];
        }
        float s  = a.x + a.y + a.z + a.w + r.x + r.y + r.z + r.w;
        float ss = a.x*a.x + a.y*a.y + a.z*a.z + a.w*a.w
                 + r.x*r.x + r.y*r.y + r.z*r.z + r.w*r.w;
        #pragma unroll
        for (int o = 16; o; o >>= 1) {
            s  += __shfl_xor_sync(0xffffffffu, s,  o);
            ss += __shfl_xor_sync(0xffffffffu, ss, o);
        }
        float mu  = s * (1.f / H2);
        float var = ss * (1.f / H2) - mu * mu;
        float rs  = rsqrtf(var + 1e-5f);

        float4 ga = *(const float4*)&g2[p];
        float4 ba = *(const float4*)&b2ln[p];
        float4 gr = *(const float4*)&g2[H + p];
        float4 br_ = *(const float4*)&b2ln[H + p];
        float4 oa, orr;
        oa.x = (a.x - mu) * rs * ga.x + ba.x;
        oa.y = (a.y - mu) * rs * ga.y + ba.y;
        oa.z = (a.z - mu) * rs * ga.z + ba.z;
        oa.w = (a.w - mu) * rs * ga.w + ba.w;
        orr.x = (r.x - mu) * rs * gr.x + br_.x;
        orr.y = (r.y - mu) * rs * gr.y + br_.y;
        orr.z = (r.z - mu) * rs * gr.z + br_.z;
        orr.w = (r.w - mu) * rs * gr.w + br_.w;
        *(float4*)&hn_s[el][p]     = oa;
        *(float4*)&hn_s[el][H + p] = orr;
    }
    __syncthreads();

    float acc[4][4];
    #pragma unroll
    for (int i = 0; i < 4; i++)
        #pragma unroll
        for (int c = 0; c < 4; c++) acc[i][c] = 0.f;

    const int j0 = lane * 4;
    const int e0 = warp * 4;

    #pragma unroll 4
    for (int k = 0; k < H2; k++) {
        float4 w = *(const float4*)&W1[k * H + j0];
        #pragma unroll
        for (int i = 0; i < 4; i++) {
            float a = hn_s[e0 + i][k];
            acc[i][0] += a * w.x; acc[i][1] += a * w.y;
            acc[i][2] += a * w.z; acc[i][3] += a * w.w;
        }
    }

    float4 b1v = *(const float4*)&b1[j0];
    float4 w2v = *(const float4*)&W2[j0];
    float  b2s = b2[0];

    #pragma unroll
    for (int i = 0; i < 4; i++) {
        float h0 = acc[i][0] + b1v.x;
        float h1 = acc[i][1] + b1v.y;
        float h2 = acc[i][2] + b1v.z;
        float h3 = acc[i][3] + b1v.w;
        h0 = (h0 > 0.f) ? h0 : expm1f(h0);
        h1 = (h1 > 0.f) ? h1 : expm1f(h1);
        h2 = (h2 > 0.f) ? h2 : expm1f(h2);
        h3 = (h3 > 0.f) ? h3 : expm1f(h3);
        float part = h0 * w2v.x + h1 * w2v.y + h2 * w2v.z + h3 * w2v.w;
        #pragma unroll
        for (int o = 16; o; o >>= 1)
            part += __shfl_xor_sync(0xffffffffu, part, o);
        if (lane == 0) {
            long long e = base + e0 + i;
            if (e < E) out[e] = part + b2s;
        }
    }
}

// ---------------------------------------------------------------------------
extern "C" void kernel_launch(void* const* d_in, const int* in_sizes, int n_in,
                              void* d_out, int out_size)
{
    const float* y   = (const float*)d_in[0];
    const int*   src = (const int*)d_in[1];
    const int*   dst = (const int*)d_in[2];

    // n_nodes may or may not be materialized as input 3 (size-1 array).
    int o = (in_sizes[3] == 1) ? 4 : 3;
    const float* ln_g = (const float*)d_in[o + 0];
    const float* ln_b = (const float*)d_in[o + 1];
    const float* Wl   = (const float*)d_in[o + 2];
    const float* bl   = (const float*)d_in[o + 3];
    const float* Wr   = (const float*)d_in[o + 4];
    const float* br   = (const float*)d_in[o + 5];
    const float* g2   = (const float*)d_in[o + 6];
    const float* b2ln = (const float*)d_in[o + 7];
    const float* W1   = (const float*)d_in[o + 8];
    const float* b1   = (const float*)d_in[o + 9];
    const float* W2   = (const float*)d_in[o + 10];
    const float* b2   = (const float*)d_in[o + 11];

    float* out = (float*)d_out;
    int E = in_sizes[0] / H;

    k_zero<<<(NMX * H + 255) / 256, 256>>>();
    k_gates<<<(E + 63) / 64, 256>>>(y, dst, ln_g, ln_b, Wl, bl, Wr, br, E);
    k_norm<<<(NMX * H + 255) / 256, 256>>>();
    k_mlp<<<(E + 31) / 32, 256>>>(src, dst, g2, b2ln, W1, b1, W2, b2, out, E);
}

// round 2
// speedup vs baseline: 1.8996x; 1.8996x over previous
#include <cuda_runtime.h>
#include <cstdint>

#define H   128
#define H2  256
#define NMX 40000

// Static scratch (allocations are forbidden).
__device__ __align__(16) float g_accL[(size_t)NMX * H];
__device__ __align__(16) float g_accR[(size_t)NMX * H];
__device__ float g_cnt[NMX];

// ---------------------------------------------------------------------------
// helpers
// ---------------------------------------------------------------------------
__device__ __forceinline__ uint32_t f2tf32(float f) {
    uint32_t u;
    asm("cvt.rna.tf32.f32 %0, %1;" : "=r"(u) : "f"(f));
    return u;
}

__device__ __forceinline__ void mma_tf32(float (&d)[4], const uint32_t (&a)[4],
                                         const uint32_t (&b)[2]) {
    asm volatile(
        "mma.sync.aligned.m16n8k8.row.col.f32.tf32.tf32.f32 "
        "{%0,%1,%2,%3}, {%4,%5,%6,%7}, {%8,%9}, {%0,%1,%2,%3};"
        : "+f"(d[0]), "+f"(d[1]), "+f"(d[2]), "+f"(d[3])
        : "r"(a[0]), "r"(a[1]), "r"(a[2]), "r"(a[3]), "r"(b[0]), "r"(b[1]));
}

__device__ __forceinline__ void red_add_v4(float* p, float x, float y, float z, float w) {
    asm volatile("red.global.add.v4.f32 [%0], {%1,%2,%3,%4};"
                 :: "l"(p), "f"(x), "f"(y), "f"(z), "f"(w) : "memory");
}

// ---------------------------------------------------------------------------
// K0: zero accumulators + counts
// ---------------------------------------------------------------------------
__global__ void k_zero() {
    int i = blockIdx.x * blockDim.x + threadIdx.x;
    int total = NMX * H;
    for (int p = i; p < total; p += gridDim.x * blockDim.x) {
        g_accL[p] = 0.f;
        g_accR[p] = 0.f;
    }
    if (i < NMX) g_cnt[i] = 0.f;
}

// ---------------------------------------------------------------------------
// K1: per-edge LayerNorm -> tf32 MMA GEMM (both gates) -> sigmoid -> RED.v4
// Tile: 64 edges x 128 cols x 2 matrices, 256 threads (8 warps).
// warp w: matrix = w>>2, col block nbase = (w&3)*32, all 64 edges.
// Per warp: 4 m-tiles (m16) x 4 n-tiles (n8), K = 128 (16 k-steps of 8).
// ---------------------------------------------------------------------------
__global__ void __launch_bounds__(256, 2) k_gates(
    const float* __restrict__ y,
    const int*   __restrict__ dst,
    const float* __restrict__ ln_g, const float* __restrict__ ln_b,
    const float* __restrict__ Wl,   const float* __restrict__ bl,
    const float* __restrict__ Wr,   const float* __restrict__ br,
    int E)
{
    __shared__ float yn_s[64][132];   // padded: bank = (4*row + col) % 32
    __shared__ int   dst_s[64];

    const int t    = threadIdx.x;
    const int warp = t >> 5;
    const int lane = t & 31;
    const int g    = lane >> 2;
    const int q    = lane & 3;
    const long long base = (long long)blockIdx.x * 64;

    if (t < 64) {
        long long e = base + t;
        int d = (e < E) ? dst[e] : -1;
        dst_s[t] = d;
        if (d >= 0) atomicAdd(&g_cnt[d], 1.0f);
    }

    // LayerNorm: each warp handles 8 edges; store tf32-rounded values.
    #pragma unroll
    for (int i = 0; i < 8; i++) {
        int el = warp * 8 + i;
        long long e = base + el;
        float4 v = make_float4(0.f, 0.f, 0.f, 0.f);
        if (e < E) v = *(const float4*)&y[e * H + lane * 4];
        float s  = v.x + v.y + v.z + v.w;
        float ss = v.x * v.x + v.y * v.y + v.z * v.z + v.w * v.w;
        #pragma unroll
        for (int o = 16; o; o >>= 1) {
            s  += __shfl_xor_sync(0xffffffffu, s,  o);
            ss += __shfl_xor_sync(0xffffffffu, ss, o);
        }
        float mu  = s * (1.f / H);
        float var = ss * (1.f / H) - mu * mu;
        float rs  = rsqrtf(var + 1e-5f);
        int p = lane * 4;
        float4 gg = *(const float4*)&ln_g[p];
        float4 bb = *(const float4*)&ln_b[p];
        float4 o4;
        o4.x = __uint_as_float(f2tf32((v.x - mu) * rs * gg.x + bb.x));
        o4.y = __uint_as_float(f2tf32((v.y - mu) * rs * gg.y + bb.y));
        o4.z = __uint_as_float(f2tf32((v.z - mu) * rs * gg.z + bb.z));
        o4.w = __uint_as_float(f2tf32((v.w - mu) * rs * gg.w + bb.w));
        *(float4*)&yn_s[el][p] = o4;
    }
    __syncthreads();

    const int mat   = warp >> 2;       // 0 = L, 1 = R
    const int nbase = (warp & 3) * 32;
    const float* __restrict__ W = mat ? Wr : Wl;

    float acc[4][4][4];
    #pragma unroll
    for (int mt = 0; mt < 4; mt++)
        #pragma unroll
        for (int nt = 0; nt < 4; nt++)
            #pragma unroll
            for (int r = 0; r < 4; r++) acc[mt][nt][r] = 0.f;

    #pragma unroll 4
    for (int k0 = 0; k0 < H; k0 += 8) {
        uint32_t a[4][4];
        #pragma unroll
        for (int mt = 0; mt < 4; mt++) {
            int r = mt * 16 + g;
            a[mt][0] = __float_as_uint(yn_s[r    ][k0 + q    ]);
            a[mt][1] = __float_as_uint(yn_s[r + 8][k0 + q    ]);
            a[mt][2] = __float_as_uint(yn_s[r    ][k0 + q + 4]);
            a[mt][3] = __float_as_uint(yn_s[r + 8][k0 + q + 4]);
        }
        uint32_t b[4][2];
        #pragma unroll
        for (int nt = 0; nt < 4; nt++) {
            int col = nbase + nt * 8 + g;
            b[nt][0] = f2tf32(W[(k0 + q    ) * H + col]);
            b[nt][1] = f2tf32(W[(k0 + q + 4) * H + col]);
        }
        #pragma unroll
        for (int mt = 0; mt < 4; mt++)
            #pragma unroll
            for (int nt = 0; nt < 4; nt++)
                mma_tf32(acc[mt][nt], a[mt], b[nt]);
    }

    const float* __restrict__ bias = mat ? br : bl;
    float* __restrict__ gacc = mat ? g_accR : g_accL;

    // Epilogue: sigmoid -> lane-pair exchange -> vectorized reduction.
    #pragma unroll
    for (int mt = 0; mt < 4; mt++) {
        #pragma unroll
        for (int half = 0; half < 2; half++) {
            int row = mt * 16 + g + half * 8;
            int d = dst_s[row];
            float v0[4], v1[4];
            #pragma unroll
            for (int nt = 0; nt < 4; nt++) {
                int c = nbase + nt * 8 + 2 * q;
                float x0 = acc[mt][nt][half * 2 + 0] + bias[c];
                float x1 = acc[mt][nt][half * 2 + 1] + bias[c + 1];
                v0[nt] = 1.f / (1.f + __expf(-x0));
                v1[nt] = 1.f / (1.f + __expf(-x1));
            }
            #pragma unroll
            for (int nt = 0; nt < 4; nt++) {
                float o0 = __shfl_xor_sync(0xffffffffu, v0[nt], 1);
                float o1 = __shfl_xor_sync(0xffffffffu, v1[nt], 1);
                if ((((nt ^ lane) & 1) == 0) && d >= 0) {
                    int colb = nbase + nt * 8 + ((lane & 2) << 1);
                    float x0, x1, x2, x3;
                    if (lane & 1) { x0 = o0; x1 = o1; x2 = v0[nt]; x3 = v1[nt]; }
                    else          { x0 = v0[nt]; x1 = v1[nt]; x2 = o0; x3 = o1; }
                    red_add_v4(&gacc[(long long)d * H + colb], x0, x1, x2, x3);
                }
            }
        }
    }
}

// ---------------------------------------------------------------------------
// K2: mean = sum / max(cnt, 1)
// ---------------------------------------------------------------------------
__global__ void k_norm() {
    int i = blockIdx.x * blockDim.x + threadIdx.x;
    if (i >= NMX * H) return;
    float c = g_cnt[i >> 7];
    float inv = 1.f / fmaxf(c, 1.f);
    g_accL[i] *= inv;
    g_accR[i] *= inv;
}

// ---------------------------------------------------------------------------
// K3: gather concat -> LN(256) -> tf32 MMA (32e x 128c x K256) -> ELU -> dot W2
// 256 threads, 8 warps: warp w -> m-tile (w&1), col block ((w>>1)*32), 4 n-tiles.
// ---------------------------------------------------------------------------
__global__ void __launch_bounds__(256) k_mlp(
    const int*   __restrict__ src,
    const int*   __restrict__ dst,
    const float* __restrict__ g2, const float* __restrict__ b2ln,
    const float* __restrict__ W1, const float* __restrict__ b1,
    const float* __restrict__ W2, const float* __restrict__ b2,
    float* __restrict__ out, int E)
{
    __shared__ float hn_s[32][260];   // padded: bank = (4*row + col) % 32
    __shared__ float red_s[32];

    const int t    = threadIdx.x;
    const int warp = t >> 5;
    const int lane = t & 31;
    const int g    = lane >> 2;
    const int q    = lane & 3;
    const long long base = (long long)blockIdx.x * 32;
    const int p = lane * 4;

    if (t < 32) red_s[t] = 0.f;

    // Gather + LayerNorm over 256; store tf32-rounded.
    #pragma unroll
    for (int i = 0; i < 4; i++) {
        int el = warp * 4 + i;
        long long e = base + el;
        float4 a = make_float4(0.f, 0.f, 0.f, 0.f);
        float4 r = make_float4(0.f, 0.f, 0.f, 0.f);
        if (e < E) {
            int sn = src[e], dn = dst[e];
            a = *(const float4*)&g_accL[(long long)sn * H + p];
            r = *(const float4*)&g_accR[(long long)dn * H + p];
        }
        float s  = a.x + a.y + a.z + a.w + r.x + r.y + r.z + r.w;
        float ss = a.x*a.x + a.y*a.y + a.z*a.z + a.w*a.w
                 + r.x*r.x + r.y*r.y + r.z*r.z + r.w*r.w;
        #pragma unroll
        for (int o = 16; o; o >>= 1) {
            s  += __shfl_xor_sync(0xffffffffu, s,  o);
            ss += __shfl_xor_sync(0xffffffffu, ss, o);
        }
        float mu  = s * (1.f / H2);
        float var = ss * (1.f / H2) - mu * mu;
        float rs  = rsqrtf(var + 1e-5f);

        float4 ga = *(const float4*)&g2[p];
        float4 ba = *(const float4*)&b2ln[p];
        float4 gr = *(const float4*)&g2[H + p];
        float4 br_ = *(const float4*)&b2ln[H + p];
        float4 oa, orr;
        oa.x = __uint_as_float(f2tf32((a.x - mu) * rs * ga.x + ba.x));
        oa.y = __uint_as_float(f2tf32((a.y - mu) * rs * ga.y + ba.y));
        oa.z = __uint_as_float(f2tf32((a.z - mu) * rs * ga.z + ba.z));
        oa.w = __uint_as_float(f2tf32((a.w - mu) * rs * ga.w + ba.w));
        orr.x = __uint_as_float(f2tf32((r.x - mu) * rs * gr.x + br_.x));
        orr.y = __uint_as_float(f2tf32((r.y - mu) * rs * gr.y + br_.y));
        orr.z = __uint_as_float(f2tf32((r.z - mu) * rs * gr.z + br_.z));
        orr.w = __uint_as_float(f2tf32((r.w - mu) * rs * gr.w + br_.w));
        *(float4*)&hn_s[el][p]     = oa;
        *(float4*)&hn_s[el][H + p] = orr;
    }
    __syncthreads();

    const int mt    = warp & 1;
    const int nbase = (warp >> 1) * 32;

    float acc[4][4];
    #pragma unroll
    for (int nt = 0; nt < 4; nt++)
        #pragma unroll
        for (int r = 0; r < 4; r++) acc[nt][r] = 0.f;

    const int r0 = mt * 16 + g;

    #pragma unroll 4
    for (int k0 = 0; k0 < H2; k0 += 8) {
        uint32_t a[4];
        a[0] = __float_as_uint(hn_s[r0    ][k0 + q    ]);
        a[1] = __float_as_uint(hn_s[r0 + 8][k0 + q    ]);
        a[2] = __float_as_uint(hn_s[r0    ][k0 + q + 4]);
        a[3] = __float_as_uint(hn_s[r0 + 8][k0 + q + 4]);
        #pragma unroll
        for (int nt = 0; nt < 4; nt++) {
            int col = nbase + nt * 8 + g;
            uint32_t b[2];
            b[0] = f2tf32(W1[(k0 + q    ) * H + col]);
            b[1] = f2tf32(W1[(k0 + q + 4) * H + col]);
            mma_tf32(acc[nt], a, b);
        }
    }

    // Epilogue: bias + ELU + dot with W2, reduce across quad and warps.
    float part0 = 0.f, part1 = 0.f;
    #pragma unroll
    for (int nt = 0; nt < 4; nt++) {
        int c = nbase + nt * 8 + 2 * q;
        float bc0 = b1[c], bc1 = b1[c + 1];
        float w0 = W2[c],  w1 = W2[c + 1];
        float h00 = acc[nt][0] + bc0; h00 = (h00 > 0.f) ? h00 : expm1f(h00);
        float h01 = acc[nt][1] + bc1; h01 = (h01 > 0.f) ? h01 : expm1f(h01);
        float h10 = acc[nt][2] + bc0; h10 = (h10 > 0.f) ? h10 : expm1f(h10);
        float h11 = acc[nt][3] + bc1; h11 = (h11 > 0.f) ? h11 : expm1f(h11);
        part0 += h00 * w0 + h01 * w1;
        part1 += h10 * w0 + h11 * w1;
    }
    part0 += __shfl_xor_sync(0xffffffffu, part0, 1);
    part0 += __shfl_xor_sync(0xffffffffu, part0, 2);
    part1 += __shfl_xor_sync(0xffffffffu, part1, 1);
    part1 += __shfl_xor_sync(0xffffffffu, part1, 2);
    if (q == 0) {
        atomicAdd(&red_s[r0],     part0);
        atomicAdd(&red_s[r0 + 8], part1);
    }
    __syncthreads();
    if (t < 32) {
        long long e = base + t;
        if (e < E) out[e] = red_s[t] + b2[0];
    }
}

// ---------------------------------------------------------------------------
extern "C" void kernel_launch(void* const* d_in, const int* in_sizes, int n_in,
                              void* d_out, int out_size)
{
    const float* y   = (const float*)d_in[0];
    const int*   src = (const int*)d_in[1];
    const int*   dst = (const int*)d_in[2];

    int o = (in_sizes[3] == 1) ? 4 : 3;
    const float* ln_g = (const float*)d_in[o + 0];
    const float* ln_b = (const float*)d_in[o + 1];
    const float* Wl   = (const float*)d_in[o + 2];
    const float* bl   = (const float*)d_in[o + 3];
    const float* Wr   = (const float*)d_in[o + 4];
    const float* br   = (const float*)d_in[o + 5];
    const float* g2   = (const float*)d_in[o + 6];
    const float* b2ln = (const float*)d_in[o + 7];
    const float* W1   = (const float*)d_in[o + 8];
    const float* b1   = (const float*)d_in[o + 9];
    const float* W2   = (const float*)d_in[o + 10];
    const float* b2   = (const float*)d_in[o + 11];

    float* out = (float*)d_out;
    int E = in_sizes[0] / H;

    k_zero<<<(NMX * H + 255) / 256, 256>>>();
    k_gates<<<(E + 63) / 64, 256>>>(y, dst, ln_g, ln_b, Wl, bl, Wr, br, E);
    k_norm<<<(NMX * H + 255) / 256, 256>>>();
    k_mlp<<<(E + 31) / 32, 256>>>(src, dst, g2, b2ln, W1, b1, W2, b2, out, E);
}